// round 11
// baseline (speedup 1.0000x reference)
#include <cuda_runtime.h>
#include <cstdint>

// map_h[b,h,s,e] = max(x[b,h,s..e]) where filled, else 0.
// Fill predicate (N=64, layers [16,8,8]), d = e-s:
//   d in [0,15]                   : all s
//   d odd in [17,31]              : s even
//   d in {35,39,...,63} (d%4==3)  : s%4==0
//
// Store-bound kernel at the DRAM write-drain wall (~5.1 TB/s observed).
// Streaming majority uses st.global.cs (evict-first semantics, no policy
// register); last-written PERSIST_TAIL_ROWS rows + mask use evict_last via
// cache_hint for whatever natural L2 retention is available (full carveout
// promotion is unavailable: device-limit changes are forbidden).

#define PERSIST_TAIL_ROWS 7000   // ~109MB tail + 8.4MB mask ~ L2 capacity

__device__ __forceinline__ uint64_t policy_evict_last() {
    uint64_t p;
    asm("createpolicy.fractional.L2::evict_last.b64 %0, 1.0;" : "=l"(p));
    return p;
}
__device__ __forceinline__ void st_last4(float4* p, float4 v, uint64_t pol) {
    asm volatile("st.global.L2::cache_hint.v4.f32 [%0], {%1,%2,%3,%4}, %5;"
                 :: "l"(p), "f"(v.x), "f"(v.y), "f"(v.z), "f"(v.w), "l"(pol)
                 : "memory");
}

__device__ __forceinline__ bool is_filled(int s, int e) {
    int d = e - s;
    if (d < 0)   return false;
    if (d <= 15) return true;
    if (d == 16) return false;
    if (d <= 31) return ((d & 1) != 0) && ((s & 1) == 0);
    if (d < 35)  return false;
    return (((d - 35) & 3) == 0) && ((s & 3) == 0);
}

template<bool PERSIST>
__device__ __forceinline__ void main_body(const float* __restrict__ xr,
                                          float4* __restrict__ orow,
                                          int eg, uint64_t pol) {
    const int e0 = 4 * eg;
    const int e1 = e0 + 1, e2 = e0 + 2, e3 = e0 + 3;

    // Range-test bases (unsigned wrap keeps test false for s < lo).
    const int r1a = e0 - 15, r1b = e1 - 15, r1c = e2 - 15, r1d = e3 - 15;
    const int r2b = e1 - 31;   // region2 for e1: s in [e1-31, e1-17], s even
    const int r2d = e3 - 31;   // region2 for e3
    const int r3d = e3 - 63;   // region3 for e3: s in [e3-63, e3-35], s%4==0

    const float NEG = -3.402823466e+38f;
    float m0 = NEG, m1 = NEG, m2 = NEG, m3 = NEG;

#define UPDATE_MAX(S)                                   \
    {                                                   \
        const float xs = xr[(S)];                       \
        if ((S) <= e3) m3 = fmaxf(m3, xs);              \
        if ((S) <= e2) m2 = fmaxf(m2, xs);              \
        if ((S) <= e1) m1 = fmaxf(m1, xs);              \
        if ((S) <= e0) m0 = fmaxf(m0, xs);              \
    }

#define EMIT(S, F0, F1, F2, F3)                                         \
    {                                                                   \
        float4 w;                                                       \
        w.x = (F0) ? m0 : 0.0f;                                         \
        w.y = (F1) ? m1 : 0.0f;                                         \
        w.z = (F2) ? m2 : 0.0f;                                         \
        w.w = (F3) ? m3 : 0.0f;                                         \
        if (PERSIST) st_last4(&orow[(S) * 16 + eg], w, pol);            \
        else         __stcs(&orow[(S) * 16 + eg], w);                   \
    }

    #pragma unroll
    for (int sb = 60; sb >= 0; sb -= 4) {
        {   // s = sb+3 (odd): region 1 only
            const int s = sb + 3;
            UPDATE_MAX(s);
            EMIT(s,
                 (unsigned)(s - r1a) <= 15u,
                 (unsigned)(s - r1b) <= 15u,
                 (unsigned)(s - r1c) <= 15u,
                 (unsigned)(s - r1d) <= 15u);
        }
        {   // s = sb+2 (even): region 1 + region 2 (e1,e3)
            const int s = sb + 2;
            UPDATE_MAX(s);
            EMIT(s,
                 (unsigned)(s - r1a) <= 15u,
                 ((unsigned)(s - r1b) <= 15u) | ((unsigned)(s - r2b) <= 14u),
                 (unsigned)(s - r1c) <= 15u,
                 ((unsigned)(s - r1d) <= 15u) | ((unsigned)(s - r2d) <= 14u));
        }
        {   // s = sb+1 (odd): region 1 only
            const int s = sb + 1;
            UPDATE_MAX(s);
            EMIT(s,
                 (unsigned)(s - r1a) <= 15u,
                 (unsigned)(s - r1b) <= 15u,
                 (unsigned)(s - r1c) <= 15u,
                 (unsigned)(s - r1d) <= 15u);
        }
        {   // s = sb (s%4==0): regions 1 + 2 (e1,e3) + 3 (e3)
            const int s = sb;
            UPDATE_MAX(s);
            EMIT(s,
                 (unsigned)(s - r1a) <= 15u,
                 ((unsigned)(s - r1b) <= 15u) | ((unsigned)(s - r2b) <= 14u),
                 (unsigned)(s - r1c) <= 15u,
                 ((unsigned)(s - r1d) <= 15u) | ((unsigned)(s - r2d) <= 14u) |
                 ((unsigned)(s - r3d) <= 28u));
        }
    }
#undef UPDATE_MAX
#undef EMIT
}

__global__ __launch_bounds__(64)
void sparseprop_kernel(const float* __restrict__ x,
                       float* __restrict__ out,
                       int B, int H, int nMainBlocks, int persistRow0) {
    const int N = 64;

    // ------- mask blocks (appended last; pattern only; persist in L2) -------
    if ((int)blockIdx.x >= nMainBlocks) {
        const uint64_t pol = policy_evict_last();
        const int b = (int)blockIdx.x - nMainBlocks;
        float4* mrow = reinterpret_cast<float4*>(
            out + (size_t)B * H * N * N + (size_t)b * (N * N));
        const int t = threadIdx.x;
        #pragma unroll
        for (int k = 0; k < 16; ++k) {
            const int idx = k * 64 + t;      // float4 index in 64x64 tile
            const int s  = idx >> 4;
            const int eg = idx & 15;
            const int e0 = 4 * eg;
            float4 mk;
            mk.x = is_filled(s, e0)     ? 1.0f : 0.0f;
            mk.y = is_filled(s, e0 + 1) ? 1.0f : 0.0f;
            mk.z = is_filled(s, e0 + 2) ? 1.0f : 0.0f;
            mk.w = is_filled(s, e0 + 3) ? 1.0f : 0.0f;
            st_last4(&mrow[idx], mk, pol);
        }
        return;
    }

    // ---------------- main blocks: map_h (4 rows per block) ----------------
    __shared__ float sx[4 * 64];

    const int row0 = (int)blockIdx.x * 4;
    const int t  = threadIdx.x;
    const int rl = t >> 4;                // 0..3 (row within block)
    const int eg = t & 15;
    const int row = row0 + rl;            // global (b*H + h)

    // Cooperative load: 4 rows x 64 floats = 64 float4, one per thread.
    reinterpret_cast<float4*>(sx)[t] =
        reinterpret_cast<const float4*>(x + (size_t)row0 * N)[t];
    __syncthreads();

    const float* xr = &sx[rl * 64];
    float4* orow = reinterpret_cast<float4*>(out + (size_t)row * (N * N));

    if (row0 >= persistRow0) {
        main_body<true>(xr, orow, eg, policy_evict_last());
    } else {
        main_body<false>(xr, orow, eg, 0ull);
    }
}

extern "C" void kernel_launch(void* const* d_in, const int* in_sizes, int n_in,
                              void* d_out, int out_size) {
    const float* x = (const float*)d_in[0];
    float* out = (float*)d_out;

    const int N = 64;
    const int H = 512;
    const int total = in_sizes[0];        // B*H*N
    const int B = total / (H * N);        // 32

    const int rows = B * H;               // 16384
    const int nMain = rows / 4;           // 4096 main blocks (4 rows each)
    const int blocks = nMain + B;         // mask blocks appended (run last)
    const int persistRow0 = rows - PERSIST_TAIL_ROWS;

    sparseprop_kernel<<<blocks, 64>>>(x, out, B, H, nMain, persistRow0);
}

// round 12
// speedup vs baseline: 1.0351x; 1.0351x over previous
#include <cuda_runtime.h>
#include <cstdint>

// map_h[b,h,s,e] = max(x[b,h,s..e]) where filled, else 0.
// Fill predicate (N=64, layers [16,8,8]), d = e-s:
//   d in [0,15]                   : all s
//   d odd in [17,31]              : s even   (=> e odd)
//   d in {35,39,...,63} (d%4==3)  : s%4==0   (=> e%4==3)
//
// TMA-store version: per-warp row pipeline. Lanes compute into a
// double-buffered SMEM stage (2KB chunks = 8 s-rows x 256B), lane 0 issues
// cp.async.bulk stores (bulk_group). Global writes bypass LSU/L1 entirely.

__device__ __forceinline__ bool is_filled(int s, int e) {
    int d = e - s;
    if (d < 0)   return false;
    if (d <= 15) return true;
    if (d == 16) return false;
    if (d <= 31) return ((d & 1) != 0) && ((s & 1) == 0);
    if (d < 35)  return false;
    return (((d - 35) & 3) == 0) && ((s & 3) == 0);
}

__global__ __launch_bounds__(128)
void sparseprop_kernel(const float* __restrict__ x,
                       float* __restrict__ out,
                       int B, int H, int nMainBlocks) {
    const int N = 64;

    // ---------------- mask blocks (pattern only, plain STG) ----------------
    if ((int)blockIdx.x >= nMainBlocks) {
        const int b = (int)blockIdx.x - nMainBlocks;
        float4* mrow = reinterpret_cast<float4*>(
            out + (size_t)B * H * N * N + (size_t)b * (N * N));
        const int t = threadIdx.x;
        #pragma unroll
        for (int k = 0; k < 8; ++k) {
            const int idx = k * 128 + t;     // float4 index in 64x64 tile
            const int s  = idx >> 4;
            const int eg = idx & 15;
            const int e0 = 4 * eg;
            float4 mk;
            mk.x = is_filled(s, e0)     ? 1.0f : 0.0f;
            mk.y = is_filled(s, e0 + 1) ? 1.0f : 0.0f;
            mk.z = is_filled(s, e0 + 2) ? 1.0f : 0.0f;
            mk.w = is_filled(s, e0 + 3) ? 1.0f : 0.0f;
            __stcs(&mrow[idx], mk);
        }
        return;
    }

    // ---------------- main blocks: 4 warps, one (b,h)-row per warp ----------
    __shared__ float  xin[4 * 64];
    __shared__ float2 stage[4][2][8 * 32];   // [warp][buf][8 s-rows x 64 floats] = 16KB

    const int t    = threadIdx.x;
    const int warp = t >> 5;
    const int lane = t & 31;
    const int row0 = (int)blockIdx.x * 4;
    const int row  = row0 + warp;

    // Cooperative input load: 4 rows x 64 floats = 128 float2.
    reinterpret_cast<float2*>(xin)[t] =
        reinterpret_cast<const float2*>(x + (size_t)row0 * N)[t];
    __syncthreads();

    const float* xr = &xin[warp * 64];
    float* orow = out + (size_t)row * (N * N);

    // Lane owns columns e0 = 2*lane (even), e1 = e0+1 (odd).
    const int e0 = 2 * lane;
    const int e1 = e0 + 1;
    const int r1a = e0 - 15, r1b = e1 - 15;   // region1 bases (width 16)
    const int r2  = e1 - 31;                  // region2 base  (width 15), e1 only
    const int r3  = e1 - 63;                  // region3 base  (width 29), e1 only
    const bool lodd = (lane & 1) != 0;        // region3 exists only if e1%4==3

    const float NEG = -3.402823466e+38f;
    float m0 = NEG, m1 = NEG;

    // Chunks of 8 s-values, descending: c = 7..0 covers s = 63..0.
    for (int c = 7; c >= 0; --c) {
        const int s0 = c * 8;
        float2* buf = stage[warp][c & 1];

        // Buffer reuse: wait until at most 1 bulk-group still reading SMEM.
        if (c <= 5) {
            if (lane == 0)
                asm volatile("cp.async.bulk.wait_group.read 1;" ::: "memory");
        }
        __syncwarp();

        #pragma unroll
        for (int k = 7; k >= 0; --k) {
            const int s = s0 + k;             // s % 4 == k % 4 (s0 % 8 == 0)
            const float xs = xr[s];
            if (s <= e1) m1 = fmaxf(m1, xs);
            if (s <= e0) m0 = fmaxf(m0, xs);

            bool f0 = (unsigned)(s - r1a) <= 15u;
            bool f1 = (unsigned)(s - r1b) <= 15u;
            if ((k & 1) == 0) {               // s even: region 2 (e1 odd)
                f1 = f1 | ((unsigned)(s - r2) <= 14u);
                if ((k & 3) == 0)             // s % 4 == 0: region 3 (e1%4==3)
                    f1 = f1 | (lodd & ((unsigned)(s - r3) <= 28u));
            }
            float2 v;
            v.x = f0 ? m0 : 0.0f;
            v.y = f1 ? m1 : 0.0f;
            buf[k * 32 + lane] = v;           // STS.64, conflict-free
        }
        __syncwarp();

        if (lane == 0) {
            // Order generic STS before async-proxy read, then bulk store 2KB.
            asm volatile("fence.proxy.async.shared::cta;" ::: "memory");
            unsigned ssrc = (unsigned)__cvta_generic_to_shared(buf);
            asm volatile(
                "cp.async.bulk.global.shared::cta.bulk_group [%0], [%1], %2;"
                :: "l"(orow + s0 * 64), "r"(ssrc), "r"(2048) : "memory");
            asm volatile("cp.async.bulk.commit_group;" ::: "memory");
        }
    }

    // Drain all outstanding bulk stores before exit.
    if (lane == 0)
        asm volatile("cp.async.bulk.wait_group 0;" ::: "memory");
}

extern "C" void kernel_launch(void* const* d_in, const int* in_sizes, int n_in,
                              void* d_out, int out_size) {
    const float* x = (const float*)d_in[0];
    float* out = (float*)d_out;

    const int N = 64;
    const int H = 512;
    const int total = in_sizes[0];        // B*H*N
    const int B = total / (H * N);        // 32

    const int rows = B * H;               // 16384
    const int nMain = rows / 4;           // 4096 main blocks (4 rows each)
    const int blocks = nMain + B;         // mask blocks appended

    sparseprop_kernel<<<blocks, 128>>>(x, out, B, H, nMain);
}